// round 9
// baseline (speedup 1.0000x reference)
#include <cuda_runtime.h>
#include <cuda_fp16.h>
#include <math.h>
#include <stdint.h>

#define NSEQ 2048
#define BATCH 2
#define HEADS 8
#define DH 64
#define KRET 32
#define DIM 512
#define NT 32

__device__ float g_q[(size_t)BATCH * HEADS * NSEQ * DH];
__device__ float g_k[(size_t)BATCH * NSEQ * DH];
__device__ float g_v[(size_t)BATCH * NSEQ * DH];
__device__ uint4 g_kf[(size_t)BATCH * NT * 1024];
__device__ uint2 g_vf[(size_t)BATCH * NT * 1024];
// fragment-major split-fp16 operand buffers
__device__ uint32_t g_xf[(size_t)256 * 32 * 32 * 8];
__device__ uint32_t g_af[(size_t)256 * 32 * 32 * 8];
__device__ uint32_t g_wqf[(size_t)64 * 32 * 32 * 4];
__device__ uint32_t g_wkvf[(size_t)16 * 32 * 32 * 4];
__device__ uint32_t g_woutf[(size_t)64 * 32 * 32 * 4];

__device__ __forceinline__ void mma16(float* d, uint32_t a0, uint32_t a1, uint32_t a2,
                                      uint32_t a3, uint32_t b0, uint32_t b1) {
    asm volatile("mma.sync.aligned.m16n8k16.row.col.f32.f16.f16.f32 "
        "{%0,%1,%2,%3}, {%4,%5,%6,%7}, {%8,%9}, {%0,%1,%2,%3};"
        : "+f"(d[0]), "+f"(d[1]), "+f"(d[2]), "+f"(d[3])
        : "r"(a0), "r"(a1), "r"(a2), "r"(a3), "r"(b0), "r"(b1));
}
__device__ __forceinline__ uint32_t h2bits(__half2 h) {
    uint32_t u; *(__half2*)&u = h; return u;
}
__device__ __forceinline__ uint32_t split_pair_h(float a, float b, uint32_t& lo) {
    __half ha = __float2half_rn(a), hb = __float2half_rn(b);
    float ra = a - __half2float(ha), rb = b - __half2float(hb);
    lo = h2bits(__floats2half2_rn(ra, rb));
    return h2bits(__halves2half2(ha, hb));
}
__device__ __forceinline__ uint32_t s2u(const void* p) {
    return (uint32_t)__cvta_generic_to_shared(p);
}
__device__ __forceinline__ void cpa16(uint32_t s, const void* g) {
    asm volatile("cp.async.cg.shared.global [%0], [%1], 16;" :: "r"(s), "l"(g) : "memory");
}

// ---------------------------------------------------------------------------
__global__ __launch_bounds__(256) void pack_x(const float* __restrict__ x)
{
    int s = blockIdx.x * 256 + threadIdx.x;
    int band = s >> 10, rem = s & 1023;
    int kfg = rem >> 5, ln = rem & 31;
    int gid = ln >> 2, tig = ln & 3;
    const float* base = x + (size_t)(band * 16 + gid) * DIM + kfg * 16 + 2 * tig;
    float2 x00 = *(const float2*)base;
    float2 x10 = *(const float2*)(base + 8 * DIM);
    float2 x01 = *(const float2*)(base + 8);
    float2 x11 = *(const float2*)(base + 8 * DIM + 8);
    uint32_t l0, l1, l2, l3;
    uint32_t h0 = split_pair_h(x00.x, x00.y, l0);
    uint32_t h1 = split_pair_h(x10.x, x10.y, l1);
    uint32_t h2 = split_pair_h(x01.x, x01.y, l2);
    uint32_t h3 = split_pair_h(x11.x, x11.y, l3);
    *(uint4*)&g_xf[(size_t)s * 8]     = make_uint4(h0, h1, h2, h3);
    *(uint4*)&g_xf[(size_t)s * 8 + 4] = make_uint4(l0, l1, l2, l3);
}

// ---------------------------------------------------------------------------
__global__ __launch_bounds__(256) void pack_w(const float* __restrict__ Wq,
                                              const float* __restrict__ Wkv,
                                              const float* __restrict__ Wout)
{
    int sel = blockIdx.y;
    const float* W = sel == 0 ? Wq : (sel == 1 ? Wkv : Wout);
    uint32_t* out  = sel == 0 ? g_wqf : (sel == 1 ? g_wkvf : g_woutf);
    int N = (sel == 1) ? 128 : 512;
    int s = blockIdx.x * 256 + threadIdx.x;
    if (s >= (N / 8) * 1024) return;
    int nfg = s >> 10, rem = s & 1023;
    int kfg = rem >> 5, ln = rem & 31;
    int gid = ln >> 2, tig = ln & 3;
    int n = nfg * 8 + gid, k0 = kfg * 16 + 2 * tig;
    uint32_t bl0, bl1;
    uint32_t bh0 = split_pair_h(W[(size_t)k0 * N + n], W[(size_t)(k0 + 1) * N + n], bl0);
    uint32_t bh1 = split_pair_h(W[(size_t)(k0 + 8) * N + n], W[(size_t)(k0 + 9) * N + n], bl1);
    *(uint4*)&out[(size_t)s * 4] = make_uint4(bh0, bh1, bl0, bl1);
}

// ---------------------------------------------------------------------------
// fp16-split GEMM from packed fragments (unchanged from R8).
// ---------------------------------------------------------------------------
__global__ __launch_bounds__(256) void gemm_f16(const uint32_t* __restrict__ APK,
                                                const uint32_t* __restrict__ BPK,
                                                float* __restrict__ C,
                                                int M, int N, int K, int mode)
{
    __shared__ uint32_t AF[2][2048];
    __shared__ uint32_t BF[2][2048];
    __shared__ float ssbuf[2][64];

    const int tid = threadIdx.x, lane = tid & 31, w = tid >> 5;
    const int mw = w & 3, nh = w >> 2;
    const int gid = lane >> 2, tig = lane & 3;
    const int r0 = blockIdx.y * 64, c0 = blockIdx.x * 64;
    const int band0 = r0 >> 4, nf0 = c0 >> 3;
    const int KFG = K >> 4, nslab = KFG >> 1;

    const uint32_t a_su[2] = {s2u(AF[0]), s2u(AF[1])};
    const uint32_t b_su[2] = {s2u(BF[0]), s2u(BF[1])};

    float S[4][4] = {};

    #pragma unroll
    for (int it = 0; it < 2; it++) {
        int idx = tid + it * 256;
        int kf2 = idx >> 8, mb = (idx >> 6) & 3, ln = (idx >> 1) & 31, hf = idx & 1;
        cpa16(a_su[0] + (((kf2 * 4 + mb) * 32 + ln) * 8 + hf * 4) * 4,
              APK + ((size_t)((band0 + mb) * KFG + kf2) * 32 + ln) * 8 + hf * 4);
        int nf = (idx >> 5) & 7, lnb = idx & 31;
        cpa16(b_su[0] + ((kf2 * 8 + nf) * 32 + lnb) * 16,
              BPK + ((size_t)((nf0 + nf) * KFG + kf2) * 32 + lnb) * 4);
    }
    asm volatile("cp.async.commit_group;" ::: "memory");

    for (int ks = 0; ks < nslab; ks++) {
        const int cur = ks & 1;
        __syncthreads();
        if (ks + 1 < nslab) {
            const int st = cur ^ 1;
            #pragma unroll
            for (int it = 0; it < 2; it++) {
                int idx = tid + it * 256;
                int kf2 = idx >> 8, mb = (idx >> 6) & 3, ln = (idx >> 1) & 31, hf = idx & 1;
                int kfg = (ks + 1) * 2 + kf2;
                cpa16(a_su[st] + (((kf2 * 4 + mb) * 32 + ln) * 8 + hf * 4) * 4,
                      APK + ((size_t)((band0 + mb) * KFG + kfg) * 32 + ln) * 8 + hf * 4);
                int nf = (idx >> 5) & 7, lnb = idx & 31;
                cpa16(b_su[st] + ((kf2 * 8 + nf) * 32 + lnb) * 16,
                      BPK + ((size_t)((nf0 + nf) * KFG + kfg) * 32 + lnb) * 4);
            }
        }
        asm volatile("cp.async.commit_group;" ::: "memory");
        asm volatile("cp.async.wait_group 1;" ::: "memory");
        __syncthreads();

        #pragma unroll
        for (int kf2 = 0; kf2 < 2; kf2++) {
            const uint32_t* ap = &AF[cur][((kf2 * 4 + mw) * 32 + lane) * 8];
            uint4 ah = *(const uint4*)ap;
            uint4 al = *(const uint4*)(ap + 4);
            #pragma unroll
            for (int nf = 0; nf < 4; nf++) {
                uint4 kb = *(const uint4*)&BF[cur][((kf2 * 8 + nh * 4 + nf) * 32 + lane) * 4];
                mma16(S[nf], ah.x, ah.y, ah.z, ah.w, kb.x, kb.y);
                mma16(S[nf], al.x, al.y, al.z, al.w, kb.x, kb.y);
                mma16(S[nf], ah.x, ah.y, ah.z, ah.w, kb.z, kb.w);
            }
        }
    }

    const int row0 = r0 + mw * 16 + gid;
    const int colw = nh * 32;

    if (mode == 0) {
        #pragma unroll
        for (int rr = 0; rr < 2; rr++)
            #pragma unroll
            for (int nf = 0; nf < 4; nf++) {
                float2 v = make_float2(S[nf][2 * rr], S[nf][2 * rr + 1]);
                *(float2*)&C[(size_t)(row0 + rr * 8) * N + c0 + colw + nf * 8 + 2 * tig] = v;
            }
        return;
    }

    bool needs_norm = (mode == 1) || (mode == 2 && blockIdx.x == 0);
    if (needs_norm) {
        #pragma unroll
        for (int rr = 0; rr < 2; rr++) {
            float ss = 0.f;
            #pragma unroll
            for (int nf = 0; nf < 4; nf++)
                ss += S[nf][2 * rr] * S[nf][2 * rr] + S[nf][2 * rr + 1] * S[nf][2 * rr + 1];
            ss += __shfl_xor_sync(0xffffffffu, ss, 1);
            ss += __shfl_xor_sync(0xffffffffu, ss, 2);
            if (tig == 0) ssbuf[nh][mw * 16 + gid + rr * 8] = ss;
        }
    }
    __syncthreads();

    if (mode == 1) {
        #pragma unroll
        for (int rr = 0; rr < 2; rr++) {
            int rloc = mw * 16 + gid + rr * 8;
            float ss = ssbuf[0][rloc] + ssbuf[1][rloc];
            float inv = 1.0f / fmaxf(sqrtf(ss), 1e-12f);
            int row = r0 + rloc;
            int bb = row >> 11, t = row & 2047;
            size_t base = (((size_t)bb * HEADS + blockIdx.x) * NSEQ + t) * DH;
            #pragma unroll
            for (int nf = 0; nf < 4; nf++) {
                float2 v = make_float2(S[nf][2 * rr] * inv, S[nf][2 * rr + 1] * inv);
                *(float2*)&g_q[base + colw + nf * 8 + 2 * tig] = v;
            }
        }
    } else {
        #pragma unroll
        for (int rr = 0; rr < 2; rr++) {
            int rloc = mw * 16 + gid + rr * 8;
            int row = r0 + rloc;
            size_t base = (size_t)row * DH;
            if (blockIdx.x == 0) {
                float ss = ssbuf[0][rloc] + ssbuf[1][rloc];
                float inv = 1.0f / fmaxf(sqrtf(ss), 1e-12f);
                #pragma unroll
                for (int nf = 0; nf < 4; nf++) {
                    float2 v = make_float2(S[nf][2 * rr] * inv, S[nf][2 * rr + 1] * inv);
                    *(float2*)&g_k[base + colw + nf * 8 + 2 * tig] = v;
                }
            } else {
                #pragma unroll
                for (int nf = 0; nf < 4; nf++) {
                    float2 v = make_float2(S[nf][2 * rr], S[nf][2 * rr + 1]);
                    *(float2*)&g_v[base + colw + nf * 8 + 2 * tig] = v;
                }
            }
        }
    }
}

// ---------------------------------------------------------------------------
__global__ __launch_bounds__(128) void pack_kv()
{
    const int kt = blockIdx.x, bb = blockIdx.y, tid = threadIdx.x;
    const size_t r0 = (size_t)bb * NSEQ + (size_t)kt * 64;
    const size_t obase = ((size_t)bb * NT + kt) * 1024;

    #pragma unroll
    for (int it = 0; it < 8; it++) {
        int s = tid + it * 128;
        int nf = s >> 7, kf = (s >> 5) & 3, lane = s & 31;
        int gid = lane >> 2, tig = lane & 3;
        size_t key = r0 + nf * 8 + gid;
        int d0 = kf * 16 + 2 * tig;
        float2 k0 = *(const float2*)&g_k[key * DH + d0];
        float2 k1 = *(const float2*)&g_k[key * DH + d0 + 8];
        uint32_t bl0, bl1;
        uint32_t bh0 = split_pair_h(k0.x, k0.y, bl0);
        uint32_t bh1 = split_pair_h(k1.x, k1.y, bl1);
        g_kf[obase + s] = make_uint4(bh0, bh1, bl0, bl1);
    }
    #pragma unroll
    for (int it = 0; it < 8; it++) {
        int s = tid + it * 128;
        int kg = s >> 8, nfd = (s >> 5) & 7, lane = s & 31;
        int gid = lane >> 2, tig = lane & 3;
        size_t key0 = r0 + kg * 16 + 2 * tig;
        int d = nfd * 8 + gid;
        uint32_t b0 = h2bits(__floats2half2_rn(g_v[key0 * DH + d], g_v[(key0 + 1) * DH + d]));
        uint32_t b1 = h2bits(__floats2half2_rn(g_v[(key0 + 8) * DH + d], g_v[(key0 + 9) * DH + d]));
        g_vf[obase + s] = make_uint2(b0, b1);
    }
}

// ---------------------------------------------------------------------------
// Flash attention: barrier-free main loop. All loop operands (K frags, V frags,
// bias) are warp-private and loaded directly from global (__ldg): g_kf/g_vf are
// L2-resident; bias LDGs are sector-aligned. Smem only for Q frags + prologue
// buffers + final merge.
// ---------------------------------------------------------------------------
__global__ __launch_bounds__(256) void attn_mma(const float* __restrict__ memkv,
                                                const float* __restrict__ rel,
                                                const float* __restrict__ scale_param)
{
    __shared__ uint32_t QF[4096];        // 16 KB: Q frags (per-mw, shared by ng)
    __shared__ float    PMEM[64 * 36];   // 9 KB  (prologue)
    __shared__ float    SCR[64 * 72];    // 18 KB: OSM (prologue, stride 68) / OMG (merge, stride 72)
    __shared__ float    RM[128], RL[128];

    float* OSM = SCR;
    float* OMG = SCR;

    const int bb = blockIdx.x, hh = blockIdx.y;
    const int qt = NT - 1 - (int)blockIdx.z;
    const int tid = threadIdx.x, lane = tid & 31, w = tid >> 5;
    const int mw = w & 3, ng = w >> 2;
    const int gid = lane >> 2, tig = lane & 3;
    const int il0 = 16 * mw + gid;
    const float scale = expf(scale_param[hh]);

    const float* relrow = rel + ((size_t)hh * NSEQ + (size_t)qt * 64) * NSEQ;

    // ---- Q fragments (built by ng==0 warps) ----
    const float* qbase = g_q + (((size_t)bb * HEADS + hh) * NSEQ + (size_t)qt * 64) * DH;
    if (ng == 0) {
        #pragma unroll
        for (int kf = 0; kf < 4; kf++) {
            int d0 = kf * 16 + 2 * tig;
            float2 q00 = *(const float2*)&qbase[il0 * DH + d0];
            float2 q10 = *(const float2*)&qbase[(il0 + 8) * DH + d0];
            float2 q01 = *(const float2*)&qbase[il0 * DH + d0 + 8];
            float2 q11 = *(const float2*)&qbase[(il0 + 8) * DH + d0 + 8];
            uint32_t al0, al1, al2, al3;
            uint32_t ah0 = split_pair_h(q00.x, q00.y, al0);
            uint32_t ah1 = split_pair_h(q10.x, q10.y, al1);
            uint32_t ah2 = split_pair_h(q01.x, q01.y, al2);
            uint32_t ah3 = split_pair_h(q11.x, q11.y, al3);
            uint32_t* qp = &QF[((mw * 4 + kf) * 32 + lane) * 8];
            *(uint4*)qp       = make_uint4(ah0, ah1, ah2, ah3);
            *(uint4*)(qp + 4) = make_uint4(al0, al1, al2, al3);
        }
    }

    // ---- memory-attention prologue (SIMT fp32), 4 threads per query ----
    {
        int qi = tid >> 2, qtr = tid & 3;
        size_t gi = (size_t)qt * 64 + qi;
        const float* qrow = qbase + qi * DH + qtr * 16;
        float4 q4[4];
        #pragma unroll
        for (int u = 0; u < 4; u++) q4[u] = *(const float4*)&qrow[u * 4];
        const float* mk = memkv + ((((size_t)bb * HEADS + hh) * NSEQ + gi) * KRET) * 128
                        + qtr * 16;
        float sj[8];
        for (int j = 0; j < 32; j++) {
            const float* kp = mk + (size_t)j * 128;
            float p = 0.f;
            #pragma unroll
            for (int u = 0; u < 4; u++) {
                float4 k4 = *(const float4*)&kp[u * 4];
                p += q4[u].x * k4.x + q4[u].y * k4.y + q4[u].z * k4.z + q4[u].w * k4.w;
            }
            p += __shfl_xor_sync(0xffffffffu, p, 1);
            p += __shfl_xor_sync(0xffffffffu, p, 2);
            if ((j & 3) == qtr) sj[j >> 2] = p * scale;
        }
        float mx = -3.0e38f;
        #pragma unroll
        for (int u = 0; u < 8; u++) mx = fmaxf(mx, sj[u]);
        mx = fmaxf(mx, __shfl_xor_sync(0xffffffffu, mx, 1));
        mx = fmaxf(mx, __shfl_xor_sync(0xffffffffu, mx, 2));
        float ls = 0.f;
        #pragma unroll
        for (int u = 0; u < 8; u++) {
            float pe = __expf(sj[u] - mx);
            ls += pe;
            PMEM[qi * 36 + u * 4 + qtr] = pe;
        }
        ls += __shfl_xor_sync(0xffffffffu, ls, 1);
        ls += __shfl_xor_sync(0xffffffffu, ls, 2);
        if (!qtr) { RM[qi] = mx; RL[qi] = ls; }
    }
    __syncthreads();

    {
        int qi = tid >> 2, qtr = tid & 3;
        size_t gi = (size_t)qt * 64 + qi;
        const float* vb = memkv + ((((size_t)bb * HEADS + hh) * NSEQ + gi) * KRET) * 128
                        + 64 + qtr * 16;
        float4 acc[4] = {};
        for (int j = 0; j < 32; j++) {
            float p = PMEM[qi * 36 + j];
            #pragma unroll
            for (int u = 0; u < 4; u++) {
                float4 v4 = *(const float4*)&vb[(size_t)j * 128 + u * 4];
                acc[u].x += p * v4.x; acc[u].y += p * v4.y;
                acc[u].z += p * v4.z; acc[u].w += p * v4.w;
            }
        }
        #pragma unroll
        for (int u = 0; u < 4; u++)
            *(float4*)&OSM[qi * 68 + qtr * 16 + u * 4] = acc[u];
    }
    __syncthreads();

    // ---- seed accumulators ----
    float O[8][4] = {}, m_r[2], l_r[2];
    if (ng == 0) {
        m_r[0] = RM[il0];     l_r[0] = RL[il0];
        m_r[1] = RM[il0 + 8]; l_r[1] = RL[il0 + 8];
        #pragma unroll
        for (int nf = 0; nf < 8; nf++) {
            O[nf][0] = OSM[il0 * 68 + nf * 8 + 2 * tig];
            O[nf][1] = OSM[il0 * 68 + nf * 8 + 2 * tig + 1];
            O[nf][2] = OSM[(il0 + 8) * 68 + nf * 8 + 2 * tig];
            O[nf][3] = OSM[(il0 + 8) * 68 + nf * 8 + 2 * tig + 1];
        }
    } else {
        m_r[0] = m_r[1] = -3.0e38f;
        l_r[0] = l_r[1] = 0.f;
    }
    __syncthreads();   // OSM reads done before OMG alias reuse at merge

    // ---- causal local tiles: BARRIER-FREE loop ----
    for (int kt = 0; kt <= qt; kt++) {
        const uint4* kfp = &g_kf[((size_t)bb * NT + kt) * 1024 + (size_t)(ng * 16) * 32 + lane];
        const uint2* vfp = &g_vf[((size_t)bb * NT + kt) * 1024 + (size_t)(ng * 16) * 32 + lane];
        const float* brow = relrow + kt * 64 + ng * 32 + 2 * tig;

        // QK^T split-fp16: K frags direct from L2
        float S[4][4] = {};
        #pragma unroll
        for (int kf = 0; kf < 4; kf++) {
            const uint32_t* qp = &QF[((mw * 4 + kf) * 32 + lane) * 8];
            uint4 ah = *(const uint4*)qp;
            uint4 al = *(const uint4*)(qp + 4);
            #pragma unroll
            for (int nf = 0; nf < 4; nf++) {
                uint4 kb = __ldg(&kfp[(nf * 4 + kf) * 32]);
                mma16(S[nf], ah.x, ah.y, ah.z, ah.w, kb.x, kb.y);
                mma16(S[nf], al.x, al.y, al.z, al.w, kb.x, kb.y);
                mma16(S[nf], ah.x, ah.y, ah.z, ah.w, kb.z, kb.w);
            }
        }

        // online softmax; bias direct from global (sector-aligned LDG.64)
        uint32_t ph[4][2];
        #pragma unroll
        for (int rr = 0; rr < 2; rr++) {
            int il = il0 + rr * 8;
            const float* bptr = brow + (size_t)il * NSEQ;
            float mx = -3.0e38f;
            #pragma unroll
            for (int nf = 0; nf < 4; nf++) {
                int colb = ng * 32 + nf * 8 + 2 * tig;
                float2 b2 = __ldg((const float2*)(bptr + nf * 8));
                float s0 = fmaf(S[nf][2 * rr], scale, b2.x);
                float s1 = fmaf(S[nf][2 * rr + 1], scale, b2.y);
                if (kt == qt) {
                    if (colb     > il) s0 = -3.0e38f;
                    if (colb + 1 > il) s1 = -3.0e38f;
                }
                S[nf][2 * rr] = s0; S[nf][2 * rr + 1] = s1;
                mx = fmaxf(mx, fmaxf(s0, s1));
            }
            mx = fmaxf(mx, __shfl_xor_sync(0xffffffffu, mx, 1));
            mx = fmaxf(mx, __shfl_xor_sync(0xffffffffu, mx, 2));
            float mnew = fmaxf(m_r[rr], mx);
            float f = __expf(m_r[rr] - mnew);
            m_r[rr] = mnew;
            float ls = 0.f;
            #pragma unroll
            for (int nf = 0; nf < 4; nf++) {
                float p0 = __expf(S[nf][2 * rr] - mnew);
                float p1 = __expf(S[nf][2 * rr + 1] - mnew);
                ls += p0 + p1;
                ph[nf][rr] = h2bits(__floats2half2_rn(p0, p1));
            }
            #pragma unroll
            for (int nf = 0; nf < 8; nf++) {
                O[nf][2 * rr]     *= f;
                O[nf][2 * rr + 1] *= f;
            }
            ls += __shfl_xor_sync(0xffffffffu, ls, 1);
            ls += __shfl_xor_sync(0xffffffffu, ls, 2);
            l_r[rr] = l_r[rr] * f + ls;
        }

        // PV fp16: V frags direct from L2, register-direct P
        #pragma unroll
        for (int kfl = 0; kfl < 2; kfl++) {
            uint32_t a0 = ph[2 * kfl][0], a1 = ph[2 * kfl][1];
            uint32_t a2 = ph[2 * kfl + 1][0], a3 = ph[2 * kfl + 1][1];
            #pragma unroll
            for (int nfd = 0; nfd < 8; nfd++) {
                uint2 vb = __ldg(&vfp[(kfl * 8 + nfd) * 32]);
                mma16(O[nfd], a0, a1, a2, a3, vb.x, vb.y);
            }
        }
    }

    // ---- 2-way merge across ng and emit gemm3 A-fragments ----
    __syncthreads();
    if (ng == 1) {
        #pragma unroll
        for (int rr = 0; rr < 2; rr++) {
            int il = il0 + rr * 8;
            RM[64 + il] = m_r[rr];
            RL[64 + il] = l_r[rr];
            #pragma unroll
            for (int nf = 0; nf < 8; nf++) {
                float2 v = make_float2(O[nf][2 * rr], O[nf][2 * rr + 1]);
                *(float2*)&OMG[il * 72 + nf * 8 + 2 * tig] = v;
            }
        }
    }
    __syncthreads();
    if (ng == 0) {
        #pragma unroll
        for (int rr = 0; rr < 2; rr++) {
            int il = il0 + rr * 8;
            float m1 = RM[64 + il], l1 = RL[64 + il];
            float m = fmaxf(m_r[rr], m1);
            float f0 = __expf(m_r[rr] - m), f1 = __expf(m1 - m);
            float inv = 1.0f / (l_r[rr] * f0 + l1 * f1);
            #pragma unroll
            for (int nf = 0; nf < 8; nf++) {
                float2 o1 = *(const float2*)&OMG[il * 72 + nf * 8 + 2 * tig];
                O[nf][2 * rr]     = (O[nf][2 * rr]     * f0 + o1.x * f1) * inv;
                O[nf][2 * rr + 1] = (O[nf][2 * rr + 1] * f0 + o1.y * f1) * inv;
            }
        }
        int band = bb * 128 + qt * 4 + mw;
        #pragma unroll
        for (int kf = 0; kf < 4; kf++) {
            uint32_t l0, l1, l2, l3;
            uint32_t h0 = split_pair_h(O[2 * kf][0],     O[2 * kf][1],     l0);
            uint32_t h1 = split_pair_h(O[2 * kf][2],     O[2 * kf][3],     l1);
            uint32_t h2 = split_pair_h(O[2 * kf + 1][0], O[2 * kf + 1][1], l2);
            uint32_t h3 = split_pair_h(O[2 * kf + 1][2], O[2 * kf + 1][3], l3);
            size_t slot = ((size_t)band * 32 + (hh * 4 + kf)) * 32 + lane;
            *(uint4*)&g_af[slot * 8]     = make_uint4(h0, h1, h2, h3);
            *(uint4*)&g_af[slot * 8 + 4] = make_uint4(l0, l1, l2, l3);
        }
    }
}

// ---------------------------------------------------------------------------
extern "C" void kernel_launch(void* const* d_in, const int* in_sizes, int n_in,
                              void* d_out, int out_size)
{
    const float* x      = (const float*)d_in[0];
    const float* memkv  = (const float*)d_in[1];
    const float* rel    = (const float*)d_in[3];
    const float* Wq     = (const float*)d_in[4];
    const float* Wkv    = (const float*)d_in[5];
    const float* Wout   = (const float*)d_in[6];
    const float* scalep = (const float*)d_in[7];
    float* out = (float*)d_out;

    void *xf, *af, *wqf, *wkvf, *woutf;
    cudaGetSymbolAddress(&xf, g_xf);
    cudaGetSymbolAddress(&af, g_af);
    cudaGetSymbolAddress(&wqf, g_wqf);
    cudaGetSymbolAddress(&wkvf, g_wkvf);
    cudaGetSymbolAddress(&woutf, g_woutf);

    const int M = BATCH * NSEQ;
    pack_x<<<1024, 256>>>(x);
    pack_w<<<dim3(256, 3), 256>>>(Wq, Wkv, Wout);
    gemm_f16<<<dim3(DIM / 64, M / 64), 256>>>((const uint32_t*)xf, (const uint32_t*)wqf,
                                              nullptr, M, DIM, DIM, 1);
    gemm_f16<<<dim3(2, M / 64), 256>>>((const uint32_t*)xf, (const uint32_t*)wkvf,
                                       nullptr, M, 2 * DH, DIM, 2);
    pack_kv<<<dim3(NT, BATCH), 128>>>();
    attn_mma<<<dim3(BATCH, HEADS, NT), 256>>>(memkv, rel, scalep);
    gemm_f16<<<dim3(DIM / 64, M / 64), 256>>>((const uint32_t*)af, (const uint32_t*)woutf,
                                              out, M, DIM, DIM, 0);
}

// round 10
// speedup vs baseline: 1.3314x; 1.3314x over previous
#include <cuda_runtime.h>
#include <cuda_fp16.h>
#include <math.h>
#include <stdint.h>

#define NSEQ 2048
#define BATCH 2
#define HEADS 8
#define DH 64
#define KRET 32
#define DIM 512
#define NT 32

__device__ float g_q[(size_t)BATCH * HEADS * NSEQ * DH];
__device__ float g_k[(size_t)BATCH * NSEQ * DH];
__device__ float g_v[(size_t)BATCH * NSEQ * DH];
__device__ uint4 g_kf[(size_t)BATCH * NT * 1024];
__device__ uint2 g_vf[(size_t)BATCH * NT * 1024];
// fragment-major split-fp16 operand buffers
__device__ uint32_t g_xf[(size_t)256 * 32 * 32 * 8];
__device__ uint32_t g_af[(size_t)256 * 32 * 32 * 8];
__device__ uint32_t g_wqf[(size_t)64 * 32 * 32 * 4];
__device__ uint32_t g_wkvf[(size_t)16 * 32 * 32 * 4];
__device__ uint32_t g_woutf[(size_t)64 * 32 * 32 * 4];

__device__ __forceinline__ void mma16(float* d, uint32_t a0, uint32_t a1, uint32_t a2,
                                      uint32_t a3, uint32_t b0, uint32_t b1) {
    asm volatile("mma.sync.aligned.m16n8k16.row.col.f32.f16.f16.f32 "
        "{%0,%1,%2,%3}, {%4,%5,%6,%7}, {%8,%9}, {%0,%1,%2,%3};"
        : "+f"(d[0]), "+f"(d[1]), "+f"(d[2]), "+f"(d[3])
        : "r"(a0), "r"(a1), "r"(a2), "r"(a3), "r"(b0), "r"(b1));
}
__device__ __forceinline__ uint32_t h2bits(__half2 h) {
    uint32_t u; *(__half2*)&u = h; return u;
}
__device__ __forceinline__ uint32_t split_pair_h(float a, float b, uint32_t& lo) {
    __half ha = __float2half_rn(a), hb = __float2half_rn(b);
    float ra = a - __half2float(ha), rb = b - __half2float(hb);
    lo = h2bits(__floats2half2_rn(ra, rb));
    return h2bits(__halves2half2(ha, hb));
}
__device__ __forceinline__ uint32_t s2u(const void* p) {
    return (uint32_t)__cvta_generic_to_shared(p);
}
__device__ __forceinline__ void cpa16(uint32_t s, const void* g) {
    asm volatile("cp.async.cg.shared.global [%0], [%1], 16;" :: "r"(s), "l"(g) : "memory");
}

// ---------------------------------------------------------------------------
__global__ __launch_bounds__(256) void pack_x(const float* __restrict__ x)
{
    int s = blockIdx.x * 256 + threadIdx.x;
    int band = s >> 10, rem = s & 1023;
    int kfg = rem >> 5, ln = rem & 31;
    int gid = ln >> 2, tig = ln & 3;
    const float* base = x + (size_t)(band * 16 + gid) * DIM + kfg * 16 + 2 * tig;
    float2 x00 = *(const float2*)base;
    float2 x10 = *(const float2*)(base + 8 * DIM);
    float2 x01 = *(const float2*)(base + 8);
    float2 x11 = *(const float2*)(base + 8 * DIM + 8);
    uint32_t l0, l1, l2, l3;
    uint32_t h0 = split_pair_h(x00.x, x00.y, l0);
    uint32_t h1 = split_pair_h(x10.x, x10.y, l1);
    uint32_t h2 = split_pair_h(x01.x, x01.y, l2);
    uint32_t h3 = split_pair_h(x11.x, x11.y, l3);
    *(uint4*)&g_xf[(size_t)s * 8]     = make_uint4(h0, h1, h2, h3);
    *(uint4*)&g_xf[(size_t)s * 8 + 4] = make_uint4(l0, l1, l2, l3);
}

// ---------------------------------------------------------------------------
__global__ __launch_bounds__(256) void pack_w(const float* __restrict__ Wq,
                                              const float* __restrict__ Wkv,
                                              const float* __restrict__ Wout)
{
    int sel = blockIdx.y;
    const float* W = sel == 0 ? Wq : (sel == 1 ? Wkv : Wout);
    uint32_t* out  = sel == 0 ? g_wqf : (sel == 1 ? g_wkvf : g_woutf);
    int N = (sel == 1) ? 128 : 512;
    int s = blockIdx.x * 256 + threadIdx.x;
    if (s >= (N / 8) * 1024) return;
    int nfg = s >> 10, rem = s & 1023;
    int kfg = rem >> 5, ln = rem & 31;
    int gid = ln >> 2, tig = ln & 3;
    int n = nfg * 8 + gid, k0 = kfg * 16 + 2 * tig;
    uint32_t bl0, bl1;
    uint32_t bh0 = split_pair_h(W[(size_t)k0 * N + n], W[(size_t)(k0 + 1) * N + n], bl0);
    uint32_t bh1 = split_pair_h(W[(size_t)(k0 + 8) * N + n], W[(size_t)(k0 + 9) * N + n], bl1);
    *(uint4*)&out[(size_t)s * 4] = make_uint4(bh0, bh1, bl0, bl1);
}

// ---------------------------------------------------------------------------
// fp16-split GEMM from packed fragments (unchanged from R8).
// ---------------------------------------------------------------------------
__global__ __launch_bounds__(256) void gemm_f16(const uint32_t* __restrict__ APK,
                                                const uint32_t* __restrict__ BPK,
                                                float* __restrict__ C,
                                                int M, int N, int K, int mode)
{
    __shared__ uint32_t AF[2][2048];
    __shared__ uint32_t BF[2][2048];
    __shared__ float ssbuf[2][64];

    const int tid = threadIdx.x, lane = tid & 31, w = tid >> 5;
    const int mw = w & 3, nh = w >> 2;
    const int gid = lane >> 2, tig = lane & 3;
    const int r0 = blockIdx.y * 64, c0 = blockIdx.x * 64;
    const int band0 = r0 >> 4, nf0 = c0 >> 3;
    const int KFG = K >> 4, nslab = KFG >> 1;

    const uint32_t a_su[2] = {s2u(AF[0]), s2u(AF[1])};
    const uint32_t b_su[2] = {s2u(BF[0]), s2u(BF[1])};

    float S[4][4] = {};

    #pragma unroll
    for (int it = 0; it < 2; it++) {
        int idx = tid + it * 256;
        int kf2 = idx >> 8, mb = (idx >> 6) & 3, ln = (idx >> 1) & 31, hf = idx & 1;
        cpa16(a_su[0] + (((kf2 * 4 + mb) * 32 + ln) * 8 + hf * 4) * 4,
              APK + ((size_t)((band0 + mb) * KFG + kf2) * 32 + ln) * 8 + hf * 4);
        int nf = (idx >> 5) & 7, lnb = idx & 31;
        cpa16(b_su[0] + ((kf2 * 8 + nf) * 32 + lnb) * 16,
              BPK + ((size_t)((nf0 + nf) * KFG + kf2) * 32 + lnb) * 4);
    }
    asm volatile("cp.async.commit_group;" ::: "memory");

    for (int ks = 0; ks < nslab; ks++) {
        const int cur = ks & 1;
        __syncthreads();
        if (ks + 1 < nslab) {
            const int st = cur ^ 1;
            #pragma unroll
            for (int it = 0; it < 2; it++) {
                int idx = tid + it * 256;
                int kf2 = idx >> 8, mb = (idx >> 6) & 3, ln = (idx >> 1) & 31, hf = idx & 1;
                int kfg = (ks + 1) * 2 + kf2;
                cpa16(a_su[st] + (((kf2 * 4 + mb) * 32 + ln) * 8 + hf * 4) * 4,
                      APK + ((size_t)((band0 + mb) * KFG + kfg) * 32 + ln) * 8 + hf * 4);
                int nf = (idx >> 5) & 7, lnb = idx & 31;
                cpa16(b_su[st] + ((kf2 * 8 + nf) * 32 + lnb) * 16,
                      BPK + ((size_t)((nf0 + nf) * KFG + kfg) * 32 + lnb) * 4);
            }
        }
        asm volatile("cp.async.commit_group;" ::: "memory");
        asm volatile("cp.async.wait_group 1;" ::: "memory");
        __syncthreads();

        #pragma unroll
        for (int kf2 = 0; kf2 < 2; kf2++) {
            const uint32_t* ap = &AF[cur][((kf2 * 4 + mw) * 32 + lane) * 8];
            uint4 ah = *(const uint4*)ap;
            uint4 al = *(const uint4*)(ap + 4);
            #pragma unroll
            for (int nf = 0; nf < 4; nf++) {
                uint4 kb = *(const uint4*)&BF[cur][((kf2 * 8 + nh * 4 + nf) * 32 + lane) * 4];
                mma16(S[nf], ah.x, ah.y, ah.z, ah.w, kb.x, kb.y);
                mma16(S[nf], al.x, al.y, al.z, al.w, kb.x, kb.y);
                mma16(S[nf], ah.x, ah.y, ah.z, ah.w, kb.z, kb.w);
            }
        }
    }

    const int row0 = r0 + mw * 16 + gid;
    const int colw = nh * 32;

    if (mode == 0) {
        #pragma unroll
        for (int rr = 0; rr < 2; rr++)
            #pragma unroll
            for (int nf = 0; nf < 4; nf++) {
                float2 v = make_float2(S[nf][2 * rr], S[nf][2 * rr + 1]);
                *(float2*)&C[(size_t)(row0 + rr * 8) * N + c0 + colw + nf * 8 + 2 * tig] = v;
            }
        return;
    }

    bool needs_norm = (mode == 1) || (mode == 2 && blockIdx.x == 0);
    if (needs_norm) {
        #pragma unroll
        for (int rr = 0; rr < 2; rr++) {
            float ss = 0.f;
            #pragma unroll
            for (int nf = 0; nf < 4; nf++)
                ss += S[nf][2 * rr] * S[nf][2 * rr] + S[nf][2 * rr + 1] * S[nf][2 * rr + 1];
            ss += __shfl_xor_sync(0xffffffffu, ss, 1);
            ss += __shfl_xor_sync(0xffffffffu, ss, 2);
            if (tig == 0) ssbuf[nh][mw * 16 + gid + rr * 8] = ss;
        }
    }
    __syncthreads();

    if (mode == 1) {
        #pragma unroll
        for (int rr = 0; rr < 2; rr++) {
            int rloc = mw * 16 + gid + rr * 8;
            float ss = ssbuf[0][rloc] + ssbuf[1][rloc];
            float inv = 1.0f / fmaxf(sqrtf(ss), 1e-12f);
            int row = r0 + rloc;
            int bb = row >> 11, t = row & 2047;
            size_t base = (((size_t)bb * HEADS + blockIdx.x) * NSEQ + t) * DH;
            #pragma unroll
            for (int nf = 0; nf < 4; nf++) {
                float2 v = make_float2(S[nf][2 * rr] * inv, S[nf][2 * rr + 1] * inv);
                *(float2*)&g_q[base + colw + nf * 8 + 2 * tig] = v;
            }
        }
    } else {
        #pragma unroll
        for (int rr = 0; rr < 2; rr++) {
            int rloc = mw * 16 + gid + rr * 8;
            int row = r0 + rloc;
            size_t base = (size_t)row * DH;
            if (blockIdx.x == 0) {
                float ss = ssbuf[0][rloc] + ssbuf[1][rloc];
                float inv = 1.0f / fmaxf(sqrtf(ss), 1e-12f);
                #pragma unroll
                for (int nf = 0; nf < 4; nf++) {
                    float2 v = make_float2(S[nf][2 * rr] * inv, S[nf][2 * rr + 1] * inv);
                    *(float2*)&g_k[base + colw + nf * 8 + 2 * tig] = v;
                }
            } else {
                #pragma unroll
                for (int nf = 0; nf < 4; nf++) {
                    float2 v = make_float2(S[nf][2 * rr], S[nf][2 * rr + 1]);
                    *(float2*)&g_v[base + colw + nf * 8 + 2 * tig] = v;
                }
            }
        }
    }
}

// ---------------------------------------------------------------------------
__global__ __launch_bounds__(128) void pack_kv()
{
    const int kt = blockIdx.x, bb = blockIdx.y, tid = threadIdx.x;
    const size_t r0 = (size_t)bb * NSEQ + (size_t)kt * 64;
    const size_t obase = ((size_t)bb * NT + kt) * 1024;

    #pragma unroll
    for (int it = 0; it < 8; it++) {
        int s = tid + it * 128;
        int nf = s >> 7, kf = (s >> 5) & 3, lane = s & 31;
        int gid = lane >> 2, tig = lane & 3;
        size_t key = r0 + nf * 8 + gid;
        int d0 = kf * 16 + 2 * tig;
        float2 k0 = *(const float2*)&g_k[key * DH + d0];
        float2 k1 = *(const float2*)&g_k[key * DH + d0 + 8];
        uint32_t bl0, bl1;
        uint32_t bh0 = split_pair_h(k0.x, k0.y, bl0);
        uint32_t bh1 = split_pair_h(k1.x, k1.y, bl1);
        g_kf[obase + s] = make_uint4(bh0, bh1, bl0, bl1);
    }
    #pragma unroll
    for (int it = 0; it < 8; it++) {
        int s = tid + it * 128;
        int kg = s >> 8, nfd = (s >> 5) & 7, lane = s & 31;
        int gid = lane >> 2, tig = lane & 3;
        size_t key0 = r0 + kg * 16 + 2 * tig;
        int d = nfd * 8 + gid;
        uint32_t b0 = h2bits(__floats2half2_rn(g_v[key0 * DH + d], g_v[(key0 + 1) * DH + d]));
        uint32_t b1 = h2bits(__floats2half2_rn(g_v[(key0 + 8) * DH + d], g_v[(key0 + 9) * DH + d]));
        g_vf[obase + s] = make_uint2(b0, b1);
    }
}

// ---------------------------------------------------------------------------
// Flash attention: R8 cp.async pipeline, but per-half-CTA (ng group) private
// staging with named barriers (bar.sync 1+ng, 128). The two 4-warp groups
// free-run; block barriers only in prologue/merge.
// smem layout (u32): QF 0..4096 | stage0 block 4096..14848 | stage1 block
// 14848..25600 | RM 25600 | RL 25728. Per stage block: KS g0(2048) KS g1(2048)
// VS g0(1024) VS g1(1024) BS g0(2304) BS g1(2304). PMEM/OSM alias stage1;
// OMG aliases stage0.
// ---------------------------------------------------------------------------
#define STB 10752
__global__ __launch_bounds__(256, 2) void attn_mma(const float* __restrict__ memkv,
                                                   const float* __restrict__ rel,
                                                   const float* __restrict__ scale_param)
{
    extern __shared__ uint32_t smu[];
    uint32_t* QF  = smu;                              // 4096
    float* PMEM = (float*)(smu + 4096 + STB);         // 2304 (aliases KS g0 s1 + pad)
    float* OSM  = (float*)(smu + 4096 + STB + 2304);  // 4352 (aliases rest of stage1)
    float* OMG  = (float*)(smu + 4096);               // 4608 (aliases stage0)
    float* RM   = (float*)(smu + 25600);              // 128
    float* RL   = RM + 128;                           // 128

    const int bb = blockIdx.x, hh = blockIdx.y;
    const int qt = NT - 1 - (int)blockIdx.z;
    const int tid = threadIdx.x, lane = tid & 31, w = tid >> 5;
    const int mw = w & 3, ng = w >> 2;
    const int g = ng, gtid = tid & 127;
    const int gid = lane >> 2, tig = lane & 3;
    const int il0 = 16 * mw + gid;
    const float scale = expf(scale_param[hh]);

    const uint32_t ks_su[2] = {s2u(smu + 4096  + g * 2048),
                               s2u(smu + 4096  + g * 2048 + STB)};
    const uint32_t vs_su[2] = {s2u(smu + 8192  + g * 1024),
                               s2u(smu + 8192  + g * 1024 + STB)};
    const uint32_t bs_su[2] = {s2u(smu + 10240 + g * 2304),
                               s2u(smu + 10240 + g * 2304 + STB)};
    const float* relrow = rel + ((size_t)hh * NSEQ + (size_t)qt * 64) * NSEQ;
    const uint4* ktile = g_kf + (size_t)bb * NT * 1024 + g * 512;
    const uint4* vtile = (const uint4*)(g_vf + (size_t)bb * NT * 1024 + g * 512);

    // ---- prefetch tile 0 into stage 0 (group-private) ----
    {
        #pragma unroll
        for (int it = 0; it < 4; it++)
            cpa16(ks_su[0] + (gtid + it * 128) * 16, ktile + gtid + it * 128);
        #pragma unroll
        for (int it = 0; it < 2; it++)
            cpa16(vs_su[0] + (gtid + it * 128) * 16, vtile + gtid + it * 128);
        const float* bsrc = relrow + g * 32;
        #pragma unroll
        for (int it = 0; it < 4; it++) {
            int c = gtid + it * 128;
            int r = c >> 3, c4 = c & 7;
            cpa16(bs_su[0] + (r * 36 + c4 * 4) * 4, bsrc + (size_t)r * NSEQ + c4 * 4);
        }
        asm volatile("cp.async.commit_group;" ::: "memory");
    }

    // ---- Q fragments (built by ng==0 warps) ----
    const float* qbase = g_q + (((size_t)bb * HEADS + hh) * NSEQ + (size_t)qt * 64) * DH;
    if (ng == 0) {
        #pragma unroll
        for (int kf = 0; kf < 4; kf++) {
            int d0 = kf * 16 + 2 * tig;
            float2 q00 = *(const float2*)&qbase[il0 * DH + d0];
            float2 q10 = *(const float2*)&qbase[(il0 + 8) * DH + d0];
            float2 q01 = *(const float2*)&qbase[il0 * DH + d0 + 8];
            float2 q11 = *(const float2*)&qbase[(il0 + 8) * DH + d0 + 8];
            uint32_t al0, al1, al2, al3;
            uint32_t ah0 = split_pair_h(q00.x, q00.y, al0);
            uint32_t ah1 = split_pair_h(q10.x, q10.y, al1);
            uint32_t ah2 = split_pair_h(q01.x, q01.y, al2);
            uint32_t ah3 = split_pair_h(q11.x, q11.y, al3);
            uint32_t* qp = &QF[((mw * 4 + kf) * 32 + lane) * 8];
            *(uint4*)qp       = make_uint4(ah0, ah1, ah2, ah3);
            *(uint4*)(qp + 4) = make_uint4(al0, al1, al2, al3);
        }
    }

    // ---- memory-attention prologue (SIMT fp32), 4 threads per query ----
    {
        int qi = tid >> 2, qtr = tid & 3;
        size_t gi = (size_t)qt * 64 + qi;
        const float* qrow = qbase + qi * DH + qtr * 16;
        float4 q4[4];
        #pragma unroll
        for (int u = 0; u < 4; u++) q4[u] = *(const float4*)&qrow[u * 4];
        const float* mk = memkv + ((((size_t)bb * HEADS + hh) * NSEQ + gi) * KRET) * 128
                        + qtr * 16;
        float sj[8];
        for (int j = 0; j < 32; j++) {
            const float* kp = mk + (size_t)j * 128;
            float p = 0.f;
            #pragma unroll
            for (int u = 0; u < 4; u++) {
                float4 k4 = *(const float4*)&kp[u * 4];
                p += q4[u].x * k4.x + q4[u].y * k4.y + q4[u].z * k4.z + q4[u].w * k4.w;
            }
            p += __shfl_xor_sync(0xffffffffu, p, 1);
            p += __shfl_xor_sync(0xffffffffu, p, 2);
            if ((j & 3) == qtr) sj[j >> 2] = p * scale;
        }
        float mx = -3.0e38f;
        #pragma unroll
        for (int u = 0; u < 8; u++) mx = fmaxf(mx, sj[u]);
        mx = fmaxf(mx, __shfl_xor_sync(0xffffffffu, mx, 1));
        mx = fmaxf(mx, __shfl_xor_sync(0xffffffffu, mx, 2));
        float ls = 0.f;
        #pragma unroll
        for (int u = 0; u < 8; u++) {
            float pe = __expf(sj[u] - mx);
            ls += pe;
            PMEM[qi * 36 + u * 4 + qtr] = pe;
        }
        ls += __shfl_xor_sync(0xffffffffu, ls, 1);
        ls += __shfl_xor_sync(0xffffffffu, ls, 2);
        if (!qtr) { RM[qi] = mx; RL[qi] = ls; }
    }
    __syncthreads();

    {
        int qi = tid >> 2, qtr = tid & 3;
        size_t gi = (size_t)qt * 64 + qi;
        const float* vb = memkv + ((((size_t)bb * HEADS + hh) * NSEQ + gi) * KRET) * 128
                        + 64 + qtr * 16;
        float4 acc[4] = {};
        for (int j = 0; j < 32; j++) {
            float p = PMEM[qi * 36 + j];
            #pragma unroll
            for (int u = 0; u < 4; u++) {
                float4 v4 = *(const float4*)&vb[(size_t)j * 128 + u * 4];
                acc[u].x += p * v4.x; acc[u].y += p * v4.y;
                acc[u].z += p * v4.z; acc[u].w += p * v4.w;
            }
        }
        #pragma unroll
        for (int u = 0; u < 4; u++)
            *(float4*)&OSM[qi * 68 + qtr * 16 + u * 4] = acc[u];
    }
    __syncthreads();

    // ---- seed accumulators ----
    float O[8][4] = {}, m_r[2], l_r[2];
    if (ng == 0) {
        m_r[0] = RM[il0];     l_r[0] = RL[il0];
        m_r[1] = RM[il0 + 8]; l_r[1] = RL[il0 + 8];
        #pragma unroll
        for (int nf = 0; nf < 8; nf++) {
            O[nf][0] = OSM[il0 * 68 + nf * 8 + 2 * tig];
            O[nf][1] = OSM[il0 * 68 + nf * 8 + 2 * tig + 1];
            O[nf][2] = OSM[(il0 + 8) * 68 + nf * 8 + 2 * tig];
            O[nf][3] = OSM[(il0 + 8) * 68 + nf * 8 + 2 * tig + 1];
        }
    } else {
        m_r[0] = m_r[1] = -3.0e38f;
        l_r[0] = l_r[1] = 0.f;
    }
    __syncthreads();   // PMEM/OSM reads done before stage-1 prefetch overwrites them

    // ---- causal local tiles: group-scoped pipeline ----
    for (int kt = 0; kt <= qt; kt++) {
        const int cur = kt & 1;
        asm volatile("bar.sync %0, 128;" :: "r"(1 + g) : "memory");
        if (kt + 1 <= qt) {
            const int st = cur ^ 1;
            const uint4* ks = ktile + (size_t)(kt + 1) * 1024;
            #pragma unroll
            for (int it = 0; it < 4; it++)
                cpa16(ks_su[st] + (gtid + it * 128) * 16, ks + gtid + it * 128);
            const uint4* vs = vtile + (size_t)(kt + 1) * 512;
            #pragma unroll
            for (int it = 0; it < 2; it++)
                cpa16(vs_su[st] + (gtid + it * 128) * 16, vs + gtid + it * 128);
            const float* bsrc = relrow + (size_t)(kt + 1) * 64 + g * 32;
            #pragma unroll
            for (int it = 0; it < 4; it++) {
                int c = gtid + it * 128;
                int r = c >> 3, c4 = c & 7;
                cpa16(bs_su[st] + (r * 36 + c4 * 4) * 4, bsrc + (size_t)r * NSEQ + c4 * 4);
            }
        }
        asm volatile("cp.async.commit_group;" ::: "memory");
        asm volatile("cp.async.wait_group 1;" ::: "memory");
        asm volatile("bar.sync %0, 128;" :: "r"(1 + g) : "memory");

        const uint32_t* KSc = smu + 4096  + g * 2048 + cur * STB;
        const uint32_t* VSc = smu + 8192  + g * 1024 + cur * STB;
        const float*    BSc = (const float*)(smu + 10240 + g * 2304 + cur * STB);

        // QK^T split-fp16 on this group's 32-key slice
        float S[4][4] = {};
        #pragma unroll
        for (int kf = 0; kf < 4; kf++) {
            const uint32_t* qp = &QF[((mw * 4 + kf) * 32 + lane) * 8];
            uint4 ah = *(const uint4*)qp;
            uint4 al = *(const uint4*)(qp + 4);
            #pragma unroll
            for (int nf = 0; nf < 4; nf++) {
                uint4 kb = *(const uint4*)&KSc[((nf * 4 + kf) * 32 + lane) * 4];
                mma16(S[nf], ah.x, ah.y, ah.z, ah.w, kb.x, kb.y);
                mma16(S[nf], al.x, al.y, al.z, al.w, kb.x, kb.y);
                mma16(S[nf], ah.x, ah.y, ah.z, ah.w, kb.z, kb.w);
            }
        }

        // online softmax; P packed to half2 in registers
        uint32_t ph[4][2];
        #pragma unroll
        for (int rr = 0; rr < 2; rr++) {
            int il = il0 + rr * 8;
            float mx = -3.0e38f;
            #pragma unroll
            for (int nf = 0; nf < 4; nf++) {
                int colb = g * 32 + nf * 8 + 2 * tig;
                float2 b2 = *(const float2*)&BSc[il * 36 + nf * 8 + 2 * tig];
                float s0 = fmaf(S[nf][2 * rr], scale, b2.x);
                float s1 = fmaf(S[nf][2 * rr + 1], scale, b2.y);
                if (kt == qt) {
                    if (colb     > il) s0 = -3.0e38f;
                    if (colb + 1 > il) s1 = -3.0e38f;
                }
                S[nf][2 * rr] = s0; S[nf][2 * rr + 1] = s1;
                mx = fmaxf(mx, fmaxf(s0, s1));
            }
            mx = fmaxf(mx, __shfl_xor_sync(0xffffffffu, mx, 1));
            mx = fmaxf(mx, __shfl_xor_sync(0xffffffffu, mx, 2));
            float mnew = fmaxf(m_r[rr], mx);
            float f = __expf(m_r[rr] - mnew);
            m_r[rr] = mnew;
            float ls = 0.f;
            #pragma unroll
            for (int nf = 0; nf < 4; nf++) {
                float p0 = __expf(S[nf][2 * rr] - mnew);
                float p1 = __expf(S[nf][2 * rr + 1] - mnew);
                ls += p0 + p1;
                ph[nf][rr] = h2bits(__floats2half2_rn(p0, p1));
            }
            #pragma unroll
            for (int nf = 0; nf < 8; nf++) {
                O[nf][2 * rr]     *= f;
                O[nf][2 * rr + 1] *= f;
            }
            ls += __shfl_xor_sync(0xffffffffu, ls, 1);
            ls += __shfl_xor_sync(0xffffffffu, ls, 2);
            l_r[rr] = l_r[rr] * f + ls;
        }

        // PV fp16
        #pragma unroll
        for (int kfl = 0; kfl < 2; kfl++) {
            uint32_t a0 = ph[2 * kfl][0], a1 = ph[2 * kfl][1];
            uint32_t a2 = ph[2 * kfl + 1][0], a3 = ph[2 * kfl + 1][1];
            #pragma unroll
            for (int nfd = 0; nfd < 8; nfd++) {
                uint2 vb = *(const uint2*)&VSc[((kfl * 8 + nfd) * 32 + lane) * 2];
                mma16(O[nfd], a0, a1, a2, a3, vb.x, vb.y);
            }
        }
    }

    // ---- 2-way merge across ng and emit gemm3 A-fragments ----
    asm volatile("cp.async.wait_group 0;" ::: "memory");
    __syncthreads();
    if (ng == 1) {
        #pragma unroll
        for (int rr = 0; rr < 2; rr++) {
            int il = il0 + rr * 8;
            RM[64 + il] = m_r[rr];
            RL[64 + il] = l_r[rr];
            #pragma unroll
            for (int nf = 0; nf < 8; nf++) {
                float2 v = make_float2(O[nf][2 * rr], O[nf][2 * rr + 1]);
                *(float2*)&OMG[il * 72 + nf * 8 + 2 * tig] = v;
            }
        }
    }
    __syncthreads();
    if (ng == 0) {
        #pragma unroll
        for (int rr = 0; rr < 2; rr++) {
            int il = il0 + rr * 8;
            float m1 = RM[64 + il], l1 = RL[64 + il];
            float m = fmaxf(m_r[rr], m1);
            float f0 = __expf(m_r[rr] - m), f1 = __expf(m1 - m);
            float inv = 1.0f / (l_r[rr] * f0 + l1 * f1);
            #pragma unroll
            for (int nf = 0; nf < 8; nf++) {
                float2 o1 = *(const float2*)&OMG[il * 72 + nf * 8 + 2 * tig];
                O[nf][2 * rr]     = (O[nf][2 * rr]     * f0 + o1.x * f1) * inv;
                O[nf][2 * rr + 1] = (O[nf][2 * rr + 1] * f0 + o1.y * f1) * inv;
            }
        }
        int band = bb * 128 + qt * 4 + mw;
        #pragma unroll
        for (int kf = 0; kf < 4; kf++) {
            uint32_t l0, l1, l2, l3;
            uint32_t h0 = split_pair_h(O[2 * kf][0],     O[2 * kf][1],     l0);
            uint32_t h1 = split_pair_h(O[2 * kf][2],     O[2 * kf][3],     l1);
            uint32_t h2 = split_pair_h(O[2 * kf + 1][0], O[2 * kf + 1][1], l2);
            uint32_t h3 = split_pair_h(O[2 * kf + 1][2], O[2 * kf + 1][3], l3);
            size_t slot = ((size_t)band * 32 + (hh * 4 + kf)) * 32 + lane;
            *(uint4*)&g_af[slot * 8]     = make_uint4(h0, h1, h2, h3);
            *(uint4*)&g_af[slot * 8 + 4] = make_uint4(l0, l1, l2, l3);
        }
    }
}

// ---------------------------------------------------------------------------
extern "C" void kernel_launch(void* const* d_in, const int* in_sizes, int n_in,
                              void* d_out, int out_size)
{
    const float* x      = (const float*)d_in[0];
    const float* memkv  = (const float*)d_in[1];
    const float* rel    = (const float*)d_in[3];
    const float* Wq     = (const float*)d_in[4];
    const float* Wkv    = (const float*)d_in[5];
    const float* Wout   = (const float*)d_in[6];
    const float* scalep = (const float*)d_in[7];
    float* out = (float*)d_out;

    void *xf, *af, *wqf, *wkvf, *woutf;
    cudaGetSymbolAddress(&xf, g_xf);
    cudaGetSymbolAddress(&af, g_af);
    cudaGetSymbolAddress(&wqf, g_wqf);
    cudaGetSymbolAddress(&wkvf, g_wkvf);
    cudaGetSymbolAddress(&woutf, g_woutf);

    const int SMEM = 25856 * (int)sizeof(uint32_t);   // 103424 B
    cudaFuncSetAttribute(attn_mma, cudaFuncAttributeMaxDynamicSharedMemorySize, SMEM);

    const int M = BATCH * NSEQ;
    pack_x<<<1024, 256>>>(x);
    pack_w<<<dim3(256, 3), 256>>>(Wq, Wkv, Wout);
    gemm_f16<<<dim3(DIM / 64, M / 64), 256>>>((const uint32_t*)xf, (const uint32_t*)wqf,
                                              nullptr, M, DIM, DIM, 1);
    gemm_f16<<<dim3(2, M / 64), 256>>>((const uint32_t*)xf, (const uint32_t*)wkvf,
                                       nullptr, M, 2 * DH, DIM, 2);
    pack_kv<<<dim3(NT, BATCH), 128>>>();
    attn_mma<<<dim3(BATCH, HEADS, NT), 256, SMEM>>>(memkv, rel, scalep);
    gemm_f16<<<dim3(DIM / 64, M / 64), 256>>>((const uint32_t*)af, (const uint32_t*)woutf,
                                              out, M, DIM, DIM, 0);
}